// round 14
// baseline (speedup 1.0000x reference)
#include <cuda_runtime.h>
#include <cuda_bf16.h>
#include <math.h>
#include <stdint.h>

// Problem constants
#define NB   4
#define C    128
#define H    64
#define W    64
#define P    4096
#define G    8
#define CG   16
#define KK   9
#define OMC  32
#define JOFF 256
#define MTOT (NB*P)       // 16384

#define NT   512          // threads per GEMM CTA (16 warps, 4m x 4n)

// ---------------------------------------------------------------------------
// Scratch
// ---------------------------------------------------------------------------
__device__ float g_val [NB * P * C];
__device__ float g_om  [NB * P * JOFF];
__device__ float g_samp[NB * P * C];

// ---------------------------------------------------------------------------
// smem layout: padded bf16 tiles, stride 136 elems (272 B rows, 16B-aligned,
// conflict-free for ldmatrix: row-to-row bank offset = 4)
// ---------------------------------------------------------------------------
#define STRA 136
#define TILEB (128 * STRA * 2)     // 34816 bytes
#define SM_AH 0
#define SM_AL (TILEB)
#define SM_BH (2 * TILEB)
#define SM_BL (3 * TILEB)
#define SM_TOTAL (4 * TILEB)       // 139264 bytes

__device__ __forceinline__ uint32_t smem_u32(const void* p) {
    uint32_t a;
    asm("{ .reg .u64 t; cvta.to.shared.u64 t, %1; cvt.u32.u64 %0, t; }" : "=r"(a) : "l"(p));
    return a;
}

#define LDSM_X4(r, a) \
    asm volatile("ldmatrix.sync.aligned.m8n8.x4.shared.b16 {%0,%1,%2,%3}, [%4];" \
        : "=r"((r)[0]), "=r"((r)[1]), "=r"((r)[2]), "=r"((r)[3]) : "r"(a))

#define LDSM_X4T(r0, r1, r2, r3, a) \
    asm volatile("ldmatrix.sync.aligned.m8n8.x4.trans.shared.b16 {%0,%1,%2,%3}, [%4];" \
        : "=r"(r0), "=r"(r1), "=r"(r2), "=r"(r3) : "r"(a))

__device__ __forceinline__ void mma16816(float* d, const uint32_t* a, const uint32_t* b) {
    asm volatile(
        "mma.sync.aligned.m16n8k16.row.col.f32.bf16.bf16.f32 "
        "{%0,%1,%2,%3}, {%4,%5,%6,%7}, {%8,%9}, {%0,%1,%2,%3};"
        : "+f"(d[0]), "+f"(d[1]), "+f"(d[2]), "+f"(d[3])
        : "r"(a[0]), "r"(a[1]), "r"(a[2]), "r"(a[3]), "r"(b[0]), "r"(b[1]));
}

__device__ __forceinline__ uint32_t pack_bf16(float a, float b) {
    __nv_bfloat162 h2 = __halves2bfloat162(__float2bfloat16(a), __float2bfloat16(b));
    return *reinterpret_cast<uint32_t*>(&h2);
}

// ---------------------------------------------------------------------------
// GEMM core: 128x128 CTA tile, K=128, 16 warps (4m x 4n), warp tile 32x32.
// Split-3: AH*BH + AH*BL + AL*BH into same fp32 accumulators. acc[2][4][4]
// ---------------------------------------------------------------------------
__device__ __forceinline__ void gemm_core(uint32_t smb, int lane, int wid,
                                          float acc[2][4][4])
{
    const int wm = wid & 3, wn = wid >> 2;
    const int mbase = wm * 32, nbase = wn * 32;

    const uint32_t aoffs[3] = {SM_AH, SM_AH, SM_AL};
    const uint32_t boffs[3] = {SM_BH, SM_BL, SM_BH};

#pragma unroll
    for (int pass = 0; pass < 3; pass++) {
        const uint32_t abase = smb + aoffs[pass];
        const uint32_t bbase = smb + boffs[pass];
#pragma unroll
        for (int kk = 0; kk < 8; kk++) {
            const int k0 = kk * 16;
            uint32_t a[2][4];
#pragma unroll
            for (int mi = 0; mi < 2; mi++) {
                int mrow = mbase + mi * 16 + (lane & 15);
                uint32_t addr = abase + (uint32_t)(mrow * STRA + k0 + (lane >> 4) * 8) * 2;
                LDSM_X4(a[mi], addr);
            }
            uint32_t b[4][2];
#pragma unroll
            for (int bj = 0; bj < 2; bj++) {
                int krow = k0 + (lane & 15);
                int ncol = nbase + bj * 16 + (lane >> 4) * 8;
                uint32_t addr = bbase + (uint32_t)(krow * STRA + ncol) * 2;
                LDSM_X4T(b[bj*2][0], b[bj*2][1], b[bj*2+1][0], b[bj*2+1][1], addr);
            }
#pragma unroll
            for (int mi = 0; mi < 2; mi++)
#pragma unroll
                for (int nt = 0; nt < 4; nt++)
                    mma16816(acc[mi][nt], a[mi], b[nt]);
        }
    }
}

// Load a 128x128 fp32 weight tile (row stride J, col offset n0), convert to
// bf16 hi/lo, store into padded smem BH/BL tiles.
__device__ __forceinline__ void load_B_f32(char* sm,
                                           const float* __restrict__ Wsrc,
                                           int J, int n0, int t)
{
#pragma unroll 4
    for (int i = t; i < 128 * 32; i += NT) {
        int k = i >> 5, jq = (i & 31) * 4;
        float4 v = *(const float4*)(Wsrc + (size_t)k * J + n0 + jq);
        float hx = __bfloat162float(__float2bfloat16(v.x));
        float hy = __bfloat162float(__float2bfloat16(v.y));
        float hz = __bfloat162float(__float2bfloat16(v.z));
        float hw = __bfloat162float(__float2bfloat16(v.w));
        uint2 hp, lp;
        hp.x = pack_bf16(hx, hy);              hp.y = pack_bf16(hz, hw);
        lp.x = pack_bf16(v.x - hx, v.y - hy);  lp.y = pack_bf16(v.z - hz, v.w - hw);
        uint32_t off = (uint32_t)(k * STRA + jq) * 2;
        *(uint2*)(sm + SM_BH + off) = hp;
        *(uint2*)(sm + SM_BL + off) = lp;
    }
}

// ---------------------------------------------------------------------------
// Merged GEMM 1+2: blockIdx.y selects the B tile / output:
//   0: w_value -> g_val (J=128, n0=0)
//   1: w_off   -> g_om  (J=256, n0=0)
//   2: w_off   -> g_om  (J=256, n0=128)
// ---------------------------------------------------------------------------
__global__ __launch_bounds__(NT, 1)
void gemm_x_kernel(const float* __restrict__ x,
                   const float* __restrict__ wv, const float* __restrict__ bv,
                   const float* __restrict__ wo, const float* __restrict__ bo)
{
    extern __shared__ char sm[];
    uint32_t smb = smem_u32(sm);
    const int t = threadIdx.x, lane = t & 31, wid = t >> 5;

    const float* Wsrc; const float* bias; float* outp; int J, n0;
    if (blockIdx.y == 0)      { Wsrc = wv; bias = bv; outp = g_val; J = 128; n0 = 0;   }
    else if (blockIdx.y == 1) { Wsrc = wo; bias = bo; outp = g_om;  J = 256; n0 = 0;   }
    else                      { Wsrc = wo; bias = bo; outp = g_om;  J = 256; n0 = 128; }

    const int mg0 = blockIdx.x * 128;
    const int nimg = mg0 >> 12;
    const int p0   = mg0 & 4095;
    const float* xn = x + (size_t)nimg * C * P + p0;

    // --- A: x^T tile -> bf16 hi/lo (transpose: m=p, k=c) ---
    {
        const int m = t & 127, ch = t >> 7;      // ch in 0..3
#pragma unroll 4
        for (int i = 0; i < 16; i++) {
            int c = (i * 4 + ch) * 2;
            float v0 = xn[(size_t)c * P + m];
            float v1 = xn[(size_t)(c + 1) * P + m];
            float h0 = __bfloat162float(__float2bfloat16(v0));
            float h1 = __bfloat162float(__float2bfloat16(v1));
            uint32_t off = (uint32_t)(m * STRA + c) * 2;
            *(uint32_t*)(sm + SM_AH + off) = pack_bf16(h0, h1);
            *(uint32_t*)(sm + SM_AL + off) = pack_bf16(v0 - h0, v1 - h1);
        }
    }
    load_B_f32(sm, Wsrc, J, n0, t);
    __syncthreads();

    float acc[2][4][4];
#pragma unroll
    for (int a = 0; a < 2; a++)
#pragma unroll
        for (int b = 0; b < 4; b++)
#pragma unroll
            for (int r = 0; r < 4; r++) acc[a][b][r] = 0.f;

    gemm_core(smb, lane, wid, acc);

    // --- epilogue: + bias, float2 stores ---
    const int wm = wid & 3, wn = wid >> 2;
    const int gid = lane >> 2, tg = lane & 3;
#pragma unroll
    for (int mi = 0; mi < 2; mi++) {
        int mrow = mg0 + wm * 32 + mi * 16 + gid;
#pragma unroll
        for (int nt = 0; nt < 4; nt++) {
            int col = n0 + wn * 32 + nt * 8 + 2 * tg;
            float bs0 = __ldg(&bias[col]), bs1 = __ldg(&bias[col + 1]);
            float2 r0 = {acc[mi][nt][0] + bs0, acc[mi][nt][1] + bs1};
            float2 r1 = {acc[mi][nt][2] + bs0, acc[mi][nt][3] + bs1};
            *(float2*)&outp[(size_t)mrow * J + col] = r0;
            *(float2*)&outp[(size_t)(mrow + 8) * J + col] = r1;
        }
    }
}

// ---------------------------------------------------------------------------
// Deformable bilinear sampling — 4-lane cooperative channel split.
// ---------------------------------------------------------------------------
__global__ __launch_bounds__(256)
void sample_kernel()
{
    int tid = blockIdx.x * blockDim.x + threadIdx.x; // NB*P*G*4 = 524288
    int cq = tid & 3;
    int g  = (tid >> 2) & 7;
    int p  = (tid >> 5) & (P - 1);
    int n  = tid >> 17;

    const float* om = g_om + (size_t)(n * P + p) * JOFF + g * OMC;
    const int h = p >> 6;
    const int w = p & 63;
    const float* valbase = g_val + (size_t)n * P * C + g * CG + cq * 4;

    // load om[0..27] via float4
    float om_[28];
    {
        const float4* om4 = (const float4*)om;
#pragma unroll
        for (int i = 0; i < 7; i++) {
            float4 q = __ldg(&om4[i]);
            om_[4*i+0] = q.x; om_[4*i+1] = q.y; om_[4*i+2] = q.z; om_[4*i+3] = q.w;
        }
    }

    float4 acc = {0.f, 0.f, 0.f, 0.f};

#pragma unroll
    for (int k = 0; k < KK; k++) {
        float ox = om_[2 * k + 0];
        float oy = om_[2 * k + 1];
        float m  = om_[18 + k];
        float sy = (float)(h + k / 3 - 1) + oy;
        float sx = (float)(w + k % 3 - 1) + ox;
        float fy = floorf(sy), fx = floorf(sx);
        float tyf = sy - fy, txf = sx - fx;
        int y0 = (int)fy, x0 = (int)fx;

#pragma unroll
        for (int dy = 0; dy < 2; dy++) {
            int iy = y0 + dy;
            if (iy < 0 || iy >= H) continue;
            float wy = dy ? tyf : (1.f - tyf);
#pragma unroll
            for (int dx = 0; dx < 2; dx++) {
                int ix = x0 + dx;
                if (ix < 0 || ix >= W) continue;
                float wx = dx ? txf : (1.f - txf);
                float wgt = wy * wx * m;
                float4 v = *(const float4*)(valbase + (size_t)(iy * W + ix) * C);
                acc.x += v.x * wgt;
                acc.y += v.y * wgt;
                acc.z += v.z * wgt;
                acc.w += v.w * wgt;
            }
        }
    }

    float* o = g_samp + (size_t)(n * P + p) * C + g * CG + cq * 4;
    *(float4*)o = acc;
}

// ---------------------------------------------------------------------------
// GEMM 3 + bias + BN + SiLU, transposed store to (N,C,H,W)
// ---------------------------------------------------------------------------
__global__ __launch_bounds__(NT, 1)
void gemm_out_kernel(const float* __restrict__ wout,
                     const float* __restrict__ bout,
                     const float* __restrict__ gamma,
                     const float* __restrict__ beta,
                     const float* __restrict__ mean,
                     const float* __restrict__ var,
                     float* __restrict__ outp)
{
    extern __shared__ char sm[];
    uint32_t smb = smem_u32(sm);
    const int t = threadIdx.x, lane = t & 31, wid = t >> 5;
    const int mg0 = blockIdx.x * 128;

    // --- A: samp tile row-major -> bf16 hi/lo ---
    {
        const float* sa = g_samp + (size_t)mg0 * C;
#pragma unroll 2
        for (int i = t; i < 128 * 32; i += NT) {
            int m = i >> 5, kq = (i & 31) * 4;
            float4 v = *(const float4*)(sa + (size_t)m * C + kq);
            float hx = __bfloat162float(__float2bfloat16(v.x));
            float hy = __bfloat162float(__float2bfloat16(v.y));
            float hz = __bfloat162float(__float2bfloat16(v.z));
            float hw = __bfloat162float(__float2bfloat16(v.w));
            uint2 hp, lp;
            hp.x = pack_bf16(hx, hy);            hp.y = pack_bf16(hz, hw);
            lp.x = pack_bf16(v.x - hx, v.y - hy); lp.y = pack_bf16(v.z - hz, v.w - hw);
            uint32_t off = (uint32_t)(m * STRA + kq) * 2;
            *(uint2*)(sm + SM_AH + off) = hp;
            *(uint2*)(sm + SM_AL + off) = lp;
        }
    }
    load_B_f32(sm, wout, 128, 0, t);
    __syncthreads();

    float acc[2][4][4];
#pragma unroll
    for (int a = 0; a < 2; a++)
#pragma unroll
        for (int b = 0; b < 4; b++)
#pragma unroll
            for (int r = 0; r < 4; r++) acc[a][b][r] = 0.f;

    gemm_core(smb, lane, wid, acc);

    // --- epilogue: bias + BN + SiLU, transposed store ---
    const int wm = wid & 3, wn = wid >> 2;
    const int gid = lane >> 2, tg = lane & 3;
    const int nimg = mg0 >> 12;
    const int pbase = (mg0 & 4095) + wm * 32;

#pragma unroll
    for (int nt = 0; nt < 4; nt++) {
        int c = wn * 32 + nt * 8 + 2 * tg;
        float iv0 = __ldg(&gamma[c])   * rsqrtf(__ldg(&var[c])   + 1e-5f);
        float iv1 = __ldg(&gamma[c+1]) * rsqrtf(__ldg(&var[c+1]) + 1e-5f);
        float ad0 = __ldg(&beta[c])   - __ldg(&mean[c])   * iv0;
        float ad1 = __ldg(&beta[c+1]) - __ldg(&mean[c+1]) * iv1;
        float bo0 = __ldg(&bout[c]), bo1 = __ldg(&bout[c+1]);
        float* out0 = outp + (size_t)(nimg * C + c)     * P;
        float* out1 = outp + (size_t)(nimg * C + c + 1) * P;
#pragma unroll
        for (int mi = 0; mi < 2; mi++) {
            int p = pbase + mi * 16 + gid;
            float v00 = (acc[mi][nt][0] + bo0) * iv0 + ad0;
            float v01 = (acc[mi][nt][1] + bo1) * iv1 + ad1;
            float v10 = (acc[mi][nt][2] + bo0) * iv0 + ad0;
            float v11 = (acc[mi][nt][3] + bo1) * iv1 + ad1;
            out0[p]     = v00 / (1.f + expf(-v00));
            out1[p]     = v01 / (1.f + expf(-v01));
            out0[p + 8] = v10 / (1.f + expf(-v10));
            out1[p + 8] = v11 / (1.f + expf(-v11));
        }
    }
}

// ---------------------------------------------------------------------------
extern "C" void kernel_launch(void* const* d_in, const int* in_sizes, int n_in,
                              void* d_out, int out_size)
{
    const float* x       = (const float*)d_in[0];
    const float* w_value = (const float*)d_in[1];
    const float* b_value = (const float*)d_in[2];
    const float* w_off   = (const float*)d_in[3];
    const float* b_off   = (const float*)d_in[4];
    const float* w_out   = (const float*)d_in[5];
    const float* b_out   = (const float*)d_in[6];
    const float* gamma   = (const float*)d_in[7];
    const float* beta    = (const float*)d_in[8];
    const float* mean    = (const float*)d_in[9];
    const float* var     = (const float*)d_in[10];
    float* out = (float*)d_out;

    cudaFuncSetAttribute(gemm_x_kernel,   cudaFuncAttributeMaxDynamicSharedMemorySize, SM_TOTAL);
    cudaFuncSetAttribute(gemm_out_kernel, cudaFuncAttributeMaxDynamicSharedMemorySize, SM_TOTAL);

    gemm_x_kernel<<<dim3(MTOT/128, 3), NT, SM_TOTAL>>>(x, w_value, b_value, w_off, b_off);
    sample_kernel<<<(NB * P * G * 4) / 256, 256>>>();
    gemm_out_kernel<<<MTOT/128, NT, SM_TOTAL>>>(w_out, b_out, gamma, beta, mean, var, out);
}

// round 17
// speedup vs baseline: 1.2019x; 1.2019x over previous
#include <cuda_runtime.h>
#include <cuda_bf16.h>
#include <math.h>
#include <stdint.h>

// Problem constants
#define NB   4
#define C    128
#define H    64
#define W    64
#define P    4096
#define G    8
#define CG   16
#define KK   9
#define OMC  32
#define JOFF 256
#define MTOT (NB*P)       // 16384

#define NT   512          // threads per GEMM CTA (16 warps, 4m x 4n)

// ---------------------------------------------------------------------------
// Scratch
// ---------------------------------------------------------------------------
__device__ float g_val [NB * P * C];
__device__ float g_om  [NB * P * JOFF];
__device__ float g_samp[NB * P * C];

// ---------------------------------------------------------------------------
// smem layout: padded bf16 tiles, stride 136 elems
// ---------------------------------------------------------------------------
#define STRA 136
#define TILEB (128 * STRA * 2)     // 34816 bytes
#define SM_AH 0
#define SM_AL (TILEB)
#define SM_BH (2 * TILEB)
#define SM_BL (3 * TILEB)
#define SM_TOTAL (4 * TILEB)       // 139264 bytes

__device__ __forceinline__ uint32_t smem_u32(const void* p) {
    uint32_t a;
    asm("{ .reg .u64 t; cvta.to.shared.u64 t, %1; cvt.u32.u64 %0, t; }" : "=r"(a) : "l"(p));
    return a;
}

#define LDSM_X4(r, a) \
    asm volatile("ldmatrix.sync.aligned.m8n8.x4.shared.b16 {%0,%1,%2,%3}, [%4];" \
        : "=r"((r)[0]), "=r"((r)[1]), "=r"((r)[2]), "=r"((r)[3]) : "r"(a))

#define LDSM_X4T(r0, r1, r2, r3, a) \
    asm volatile("ldmatrix.sync.aligned.m8n8.x4.trans.shared.b16 {%0,%1,%2,%3}, [%4];" \
        : "=r"(r0), "=r"(r1), "=r"(r2), "=r"(r3) : "r"(a))

__device__ __forceinline__ void mma16816(float* d, const uint32_t* a, const uint32_t* b) {
    asm volatile(
        "mma.sync.aligned.m16n8k16.row.col.f32.bf16.bf16.f32 "
        "{%0,%1,%2,%3}, {%4,%5,%6,%7}, {%8,%9}, {%0,%1,%2,%3};"
        : "+f"(d[0]), "+f"(d[1]), "+f"(d[2]), "+f"(d[3])
        : "r"(a[0]), "r"(a[1]), "r"(a[2]), "r"(a[3]), "r"(b[0]), "r"(b[1]));
}

__device__ __forceinline__ uint32_t pack_bf16(float a, float b) {
    __nv_bfloat162 h2 = __halves2bfloat162(__float2bfloat16(a), __float2bfloat16(b));
    return *reinterpret_cast<uint32_t*>(&h2);
}

// ---------------------------------------------------------------------------
// Fused GEMM core: 128x128 CTA tile, K=128, 16 warps (4m x 4n), warp 32x32.
// Per k-step: load aH,aL,bH,bL fragments once, issue all 24 MMAs of the
// split-3 product (AH*BH + AH*BL + AL*BH).
// ---------------------------------------------------------------------------
__device__ __forceinline__ void gemm_core_fused(uint32_t smb, int lane, int wid,
                                                float acc[2][4][4])
{
    const int wm = wid & 3, wn = wid >> 2;
    const int mbase = wm * 32, nbase = wn * 32;

#pragma unroll
    for (int kk = 0; kk < 8; kk++) {
        const int k0 = kk * 16;
        uint32_t aH[2][4], aL[2][4];
#pragma unroll
        for (int mi = 0; mi < 2; mi++) {
            int mrow = mbase + mi * 16 + (lane & 15);
            uint32_t off = (uint32_t)(mrow * STRA + k0 + (lane >> 4) * 8) * 2;
            LDSM_X4(aH[mi], smb + SM_AH + off);
            LDSM_X4(aL[mi], smb + SM_AL + off);
        }
        uint32_t bH[4][2], bL[4][2];
#pragma unroll
        for (int bj = 0; bj < 2; bj++) {
            int krow = k0 + (lane & 15);
            int ncol = nbase + bj * 16 + (lane >> 4) * 8;
            uint32_t off = (uint32_t)(krow * STRA + ncol) * 2;
            LDSM_X4T(bH[bj*2][0], bH[bj*2][1], bH[bj*2+1][0], bH[bj*2+1][1], smb + SM_BH + off);
            LDSM_X4T(bL[bj*2][0], bL[bj*2][1], bL[bj*2+1][0], bL[bj*2+1][1], smb + SM_BL + off);
        }
#pragma unroll
        for (int mi = 0; mi < 2; mi++)
#pragma unroll
            for (int nt = 0; nt < 4; nt++) {
                mma16816(acc[mi][nt], aH[mi], bH[nt]);
                mma16816(acc[mi][nt], aH[mi], bL[nt]);
                mma16816(acc[mi][nt], aL[mi], bH[nt]);
            }
    }
}

// B tile gmem->reg prefetch (8 float4 per thread) and reg->smem hi/lo store
__device__ __forceinline__ void ldgB(const float* __restrict__ Wt, int J, int n0,
                                     int t, float4 r[8])
{
#pragma unroll
    for (int l = 0; l < 8; l++) {
        int idx = t + l * NT;
        int k = idx >> 5, jq = (idx & 31) * 4;
        r[l] = __ldg((const float4*)(Wt + (size_t)k * J + n0 + jq));
    }
}

__device__ __forceinline__ void stsB(char* sm, int t, const float4 r[8])
{
#pragma unroll
    for (int l = 0; l < 8; l++) {
        int idx = t + l * NT;
        int k = idx >> 5, jq = (idx & 31) * 4;
        float4 v = r[l];
        float hx = __bfloat162float(__float2bfloat16(v.x));
        float hy = __bfloat162float(__float2bfloat16(v.y));
        float hz = __bfloat162float(__float2bfloat16(v.z));
        float hw = __bfloat162float(__float2bfloat16(v.w));
        uint2 hp, lp;
        hp.x = pack_bf16(hx, hy);              hp.y = pack_bf16(hz, hw);
        lp.x = pack_bf16(v.x - hx, v.y - hy);  lp.y = pack_bf16(v.z - hz, v.w - hw);
        uint32_t off = (uint32_t)(k * STRA + jq) * 2;
        *(uint2*)(sm + SM_BH + off) = hp;
        *(uint2*)(sm + SM_BL + off) = lp;
    }
}

// ---------------------------------------------------------------------------
// GEMM 1+2, persistent over 3 B tiles: A (x^T) converted ONCE, then
//   tile 0: w_value -> g_val (J=128, n0=0)
//   tile 1: w_off   -> g_om  (J=256, n0=0)
//   tile 2: w_off   -> g_om  (J=256, n0=128)
// B(tile+1) is LDG-prefetched right after MMA and STS'd after the epilogue.
// ---------------------------------------------------------------------------
__global__ __launch_bounds__(NT, 1)
void gemm_x_kernel(const float* __restrict__ x,
                   const float* __restrict__ wv, const float* __restrict__ bv,
                   const float* __restrict__ wo, const float* __restrict__ bo)
{
    extern __shared__ char sm[];
    uint32_t smb = smem_u32(sm);
    const int t = threadIdx.x, lane = t & 31, wid = t >> 5;

    const int mg0 = blockIdx.x * 128;
    const int nimg = mg0 >> 12;
    const int p0   = mg0 & 4095;
    const float* xn = x + (size_t)nimg * C * P + p0;

    // --- A: x^T tile -> bf16 hi/lo (transpose: m=p, k=c), once ---
    {
        const int m = t & 127, ch = t >> 7;      // ch in 0..3
#pragma unroll 4
        for (int i = 0; i < 16; i++) {
            int c = (i * 4 + ch) * 2;
            float v0 = xn[(size_t)c * P + m];
            float v1 = xn[(size_t)(c + 1) * P + m];
            float h0 = __bfloat162float(__float2bfloat16(v0));
            float h1 = __bfloat162float(__float2bfloat16(v1));
            uint32_t off = (uint32_t)(m * STRA + c) * 2;
            *(uint32_t*)(sm + SM_AH + off) = pack_bf16(h0, h1);
            *(uint32_t*)(sm + SM_AL + off) = pack_bf16(v0 - h0, v1 - h1);
        }
    }

    // --- B0 (w_value) ---
    {
        float4 b0[8];
        ldgB(wv, 128, 0, t, b0);
        stsB(sm, t, b0);
    }
    __syncthreads();

    const int wm = wid & 3, wn = wid >> 2;
    const int gid = lane >> 2, tg = lane & 3;

#pragma unroll 1
    for (int tile = 0; tile < 3; tile++) {
        float acc[2][4][4];
#pragma unroll
        for (int a = 0; a < 2; a++)
#pragma unroll
            for (int b = 0; b < 4; b++)
#pragma unroll
                for (int r = 0; r < 4; r++) acc[a][b][r] = 0.f;

        gemm_core_fused(smb, lane, wid, acc);
        __syncthreads();              // all warps done reading B smem

        // prefetch next B while the epilogue stores run
        float4 bnext[8];
        if (tile == 0)      ldgB(wo, 256, 0,   t, bnext);
        else if (tile == 1) ldgB(wo, 256, 128, t, bnext);

        const float* bias = (tile == 0) ? bv : bo;
        float* outp       = (tile == 0) ? g_val : g_om;
        const int J  = (tile == 0) ? 128 : 256;
        const int n0 = (tile == 2) ? 128 : 0;

#pragma unroll
        for (int mi = 0; mi < 2; mi++) {
            int mrow = mg0 + wm * 32 + mi * 16 + gid;
#pragma unroll
            for (int nt = 0; nt < 4; nt++) {
                int col = n0 + wn * 32 + nt * 8 + 2 * tg;
                float bs0 = __ldg(&bias[col]), bs1 = __ldg(&bias[col + 1]);
                float2 r0 = {acc[mi][nt][0] + bs0, acc[mi][nt][1] + bs1};
                float2 r1 = {acc[mi][nt][2] + bs0, acc[mi][nt][3] + bs1};
                *(float2*)&outp[(size_t)mrow * J + col] = r0;
                *(float2*)&outp[(size_t)(mrow + 8) * J + col] = r1;
            }
        }

        if (tile < 2) {
            stsB(sm, t, bnext);
            __syncthreads();          // new B visible before next gemm_core
        }
    }
}

// ---------------------------------------------------------------------------
// Deformable bilinear sampling — 4-lane cooperative channel split.
// ---------------------------------------------------------------------------
__global__ __launch_bounds__(256)
void sample_kernel()
{
    int tid = blockIdx.x * blockDim.x + threadIdx.x; // NB*P*G*4 = 524288
    int cq = tid & 3;
    int g  = (tid >> 2) & 7;
    int p  = (tid >> 5) & (P - 1);
    int n  = tid >> 17;

    const float* om = g_om + (size_t)(n * P + p) * JOFF + g * OMC;
    const int h = p >> 6;
    const int w = p & 63;
    const float* valbase = g_val + (size_t)n * P * C + g * CG + cq * 4;

    // load om[0..27] via float4
    float om_[28];
    {
        const float4* om4 = (const float4*)om;
#pragma unroll
        for (int i = 0; i < 7; i++) {
            float4 q = __ldg(&om4[i]);
            om_[4*i+0] = q.x; om_[4*i+1] = q.y; om_[4*i+2] = q.z; om_[4*i+3] = q.w;
        }
    }

    float4 acc = {0.f, 0.f, 0.f, 0.f};

#pragma unroll
    for (int k = 0; k < KK; k++) {
        float ox = om_[2 * k + 0];
        float oy = om_[2 * k + 1];
        float m  = om_[18 + k];
        float sy = (float)(h + k / 3 - 1) + oy;
        float sx = (float)(w + k % 3 - 1) + ox;
        float fy = floorf(sy), fx = floorf(sx);
        float tyf = sy - fy, txf = sx - fx;
        int y0 = (int)fy, x0 = (int)fx;

#pragma unroll
        for (int dy = 0; dy < 2; dy++) {
            int iy = y0 + dy;
            if (iy < 0 || iy >= H) continue;
            float wy = dy ? tyf : (1.f - tyf);
#pragma unroll
            for (int dx = 0; dx < 2; dx++) {
                int ix = x0 + dx;
                if (ix < 0 || ix >= W) continue;
                float wx = dx ? txf : (1.f - txf);
                float wgt = wy * wx * m;
                float4 v = *(const float4*)(valbase + (size_t)(iy * W + ix) * C);
                acc.x += v.x * wgt;
                acc.y += v.y * wgt;
                acc.z += v.z * wgt;
                acc.w += v.w * wgt;
            }
        }
    }

    float* o = g_samp + (size_t)(n * P + p) * C + g * CG + cq * 4;
    *(float4*)o = acc;
}

// ---------------------------------------------------------------------------
// GEMM 3 + bias + BN + SiLU, transposed store to (N,C,H,W)
// ---------------------------------------------------------------------------
__global__ __launch_bounds__(NT, 1)
void gemm_out_kernel(const float* __restrict__ wout,
                     const float* __restrict__ bout,
                     const float* __restrict__ gamma,
                     const float* __restrict__ beta,
                     const float* __restrict__ mean,
                     const float* __restrict__ var,
                     float* __restrict__ outp)
{
    extern __shared__ char sm[];
    uint32_t smb = smem_u32(sm);
    const int t = threadIdx.x, lane = t & 31, wid = t >> 5;
    const int mg0 = blockIdx.x * 128;

    // --- A: samp tile row-major -> bf16 hi/lo ---
    {
        const float* sa = g_samp + (size_t)mg0 * C;
#pragma unroll 2
        for (int i = t; i < 128 * 32; i += NT) {
            int m = i >> 5, kq = (i & 31) * 4;
            float4 v = *(const float4*)(sa + (size_t)m * C + kq);
            float hx = __bfloat162float(__float2bfloat16(v.x));
            float hy = __bfloat162float(__float2bfloat16(v.y));
            float hz = __bfloat162float(__float2bfloat16(v.z));
            float hw = __bfloat162float(__float2bfloat16(v.w));
            uint2 hp, lp;
            hp.x = pack_bf16(hx, hy);            hp.y = pack_bf16(hz, hw);
            lp.x = pack_bf16(v.x - hx, v.y - hy); lp.y = pack_bf16(v.z - hz, v.w - hw);
            uint32_t off = (uint32_t)(m * STRA + kq) * 2;
            *(uint2*)(sm + SM_AH + off) = hp;
            *(uint2*)(sm + SM_AL + off) = lp;
        }
    }
    {
        float4 b0[8];
        ldgB(wout, 128, 0, t, b0);
        stsB(sm, t, b0);
    }
    __syncthreads();

    float acc[2][4][4];
#pragma unroll
    for (int a = 0; a < 2; a++)
#pragma unroll
        for (int b = 0; b < 4; b++)
#pragma unroll
            for (int r = 0; r < 4; r++) acc[a][b][r] = 0.f;

    gemm_core_fused(smb, lane, wid, acc);

    // --- epilogue: bias + BN + SiLU, transposed store ---
    const int wm = wid & 3, wn = wid >> 2;
    const int gid = lane >> 2, tg = lane & 3;
    const int nimg = mg0 >> 12;
    const int pbase = (mg0 & 4095) + wm * 32;

#pragma unroll
    for (int nt = 0; nt < 4; nt++) {
        int c = wn * 32 + nt * 8 + 2 * tg;
        float iv0 = __ldg(&gamma[c])   * rsqrtf(__ldg(&var[c])   + 1e-5f);
        float iv1 = __ldg(&gamma[c+1]) * rsqrtf(__ldg(&var[c+1]) + 1e-5f);
        float ad0 = __ldg(&beta[c])   - __ldg(&mean[c])   * iv0;
        float ad1 = __ldg(&beta[c+1]) - __ldg(&mean[c+1]) * iv1;
        float bo0 = __ldg(&bout[c]), bo1 = __ldg(&bout[c+1]);
        float* out0 = outp + (size_t)(nimg * C + c)     * P;
        float* out1 = outp + (size_t)(nimg * C + c + 1) * P;
#pragma unroll
        for (int mi = 0; mi < 2; mi++) {
            int p = pbase + mi * 16 + gid;
            float v00 = (acc[mi][nt][0] + bo0) * iv0 + ad0;
            float v01 = (acc[mi][nt][1] + bo1) * iv1 + ad1;
            float v10 = (acc[mi][nt][2] + bo0) * iv0 + ad0;
            float v11 = (acc[mi][nt][3] + bo1) * iv1 + ad1;
            out0[p]     = v00 / (1.f + expf(-v00));
            out1[p]     = v01 / (1.f + expf(-v01));
            out0[p + 8] = v10 / (1.f + expf(-v10));
            out1[p + 8] = v11 / (1.f + expf(-v11));
        }
    }
}

// ---------------------------------------------------------------------------
extern "C" void kernel_launch(void* const* d_in, const int* in_sizes, int n_in,
                              void* d_out, int out_size)
{
    const float* x       = (const float*)d_in[0];
    const float* w_value = (const float*)d_in[1];
    const float* b_value = (const float*)d_in[2];
    const float* w_off   = (const float*)d_in[3];
    const float* b_off   = (const float*)d_in[4];
    const float* w_out   = (const float*)d_in[5];
    const float* b_out   = (const float*)d_in[6];
    const float* gamma   = (const float*)d_in[7];
    const float* beta    = (const float*)d_in[8];
    const float* mean    = (const float*)d_in[9];
    const float* var     = (const float*)d_in[10];
    float* out = (float*)d_out;

    cudaFuncSetAttribute(gemm_x_kernel,   cudaFuncAttributeMaxDynamicSharedMemorySize, SM_TOTAL);
    cudaFuncSetAttribute(gemm_out_kernel, cudaFuncAttributeMaxDynamicSharedMemorySize, SM_TOTAL);

    gemm_x_kernel<<<MTOT/128, NT, SM_TOTAL>>>(x, w_value, b_value, w_off, b_off);
    sample_kernel<<<(NB * P * G * 4) / 256, 256>>>();
    gemm_out_kernel<<<MTOT/128, NT, SM_TOTAL>>>(w_out, b_out, gamma, beta, mean, var, out);
}